// round 14
// baseline (speedup 1.0000x reference)
#include <cuda_runtime.h>
#include <cuda_bf16.h>
#include <cstdint>

// ---------------------------------------------------------------------------
// Mamba block. bf16 mma.sync GEMMs: 128x64 tiles, warp tile 32x32 (no spills),
// 4-stage cp.async, fragment double-buffering. Scan: 1-wave grid (128x512).
// ---------------------------------------------------------------------------

#define R_TOT   2048
#define DM      1024
#define DI      2048
#define DTR     64
#define DST     16
#define XS2     8
#define PSTR    128
#define TCH     64

// fp32 scratch
__device__ float g_projp [XS2 * R_TOT * PSTR];
__device__ float g_dt    [R_TOT * DI];
// bf16 scratch
__device__ __nv_bfloat16 g_xzb [R_TOT * 2 * DI];
__device__ __nv_bfloat16 g_xnb [R_TOT * DM];
__device__ __nv_bfloat16 g_ub  [R_TOT * DI];
__device__ __nv_bfloat16 g_pjb [R_TOT * PSTR];
__device__ __nv_bfloat16 g_yb  [R_TOT * DI];
__device__ __nv_bfloat16 g_w1b [2 * DI * DM];
__device__ __nv_bfloat16 g_w2b [DI * DTR];
__device__ __nv_bfloat16 g_w3b [DM * DI];
__device__ __nv_bfloat16 g_wxb [128 * DI];

// ---------------------------------------------------------------------------
__device__ __forceinline__ uint32_t smem_u32(const void* p) {
    uint32_t a;
    asm("{ .reg .u64 t; cvta.to.shared.u64 t, %1; cvt.u32.u64 %0, t; }"
        : "=r"(a) : "l"(p));
    return a;
}
__device__ __forceinline__ uint32_t pack_bf2(float x, float y) {
    __nv_bfloat162 h = __floats2bfloat162_rn(x, y);
    return *(uint32_t*)&h;
}

#define LDSM_X4(r0, r1, r2, r3, addr)                                          \
    asm volatile("ldmatrix.sync.aligned.m8n8.x4.shared.b16 {%0,%1,%2,%3}, [%4];" \
                 : "=r"(r0), "=r"(r1), "=r"(r2), "=r"(r3) : "r"(addr))

#define MMA_BF16(d, a0, a1, a2, a3, b0, b1)                                    \
    asm volatile("mma.sync.aligned.m16n8k16.row.col.f32.bf16.bf16.f32 "        \
                 "{%0,%1,%2,%3}, {%4,%5,%6,%7}, {%8,%9}, {%0,%1,%2,%3};"       \
                 : "+f"(d[0]), "+f"(d[1]), "+f"(d[2]), "+f"(d[3])              \
                 : "r"(a0), "r"(a1), "r"(a2), "r"(a3), "r"(b0), "r"(b1))

#define CP16(saddr, gptr)                                                      \
    asm volatile("cp.async.cg.shared.global [%0], [%1], 16;"                   \
                 :: "r"(saddr), "l"(gptr))
#define CP_COMMIT() asm volatile("cp.async.commit_group;" ::: "memory")
#define CP_WAIT0()  asm volatile("cp.async.wait_group 0;" ::: "memory")
#define CP_WAIT1()  asm volatile("cp.async.wait_group 1;" ::: "memory")
#define CP_WAIT2()  asm volatile("cp.async.wait_group 2;" ::: "memory")

// ---------------------------------------------------------------------------
// bf16 GEMM: C[m,n] = sum_k A[m,k]*B[n,k]; CTA tile 128x64, BK=64, 4-stage,
// 8 warps (4m x 2n), warp tile 32x32, fragment double-buffering.
// grid (nTiles=N/64, mTiles=M/128, kSplits). epi: 0 fp32, 1 softplus(+bias),
// 2 fp32+resid, 4 bf16 store.
// ---------------------------------------------------------------------------
#define STG3      24576                  // A 16K + B 8K
#define SMEM_DYN3 (4 * STG3)             // 98304

struct Frag { uint32_t a[2][4]; uint32_t b[4][2]; };

__device__ __forceinline__ void ld_frags(
    Frag& f, uint32_t sS, int ks,
    const uint32_t* aOff, const uint32_t* bOff,
    uint32_t lane, uint32_t lk)
{
    const uint32_t swA = (uint32_t)((ks * 2 + (lane >> 4)) ^ lk) << 4;
    const uint32_t swB = (uint32_t)((ks * 2 + ((lane >> 3) & 1)) ^ lk) << 4;
    #pragma unroll
    for (int mi = 0; mi < 2; mi++)
        LDSM_X4(f.a[mi][0], f.a[mi][1], f.a[mi][2], f.a[mi][3],
                sS + aOff[mi] + swA);
    #pragma unroll
    for (int nj = 0; nj < 2; nj++) {
        uint32_t r0, r1, r2, r3;
        LDSM_X4(r0, r1, r2, r3, sS + bOff[nj] + swB);
        f.b[2 * nj][0] = r0; f.b[2 * nj][1] = r1;
        f.b[2 * nj + 1][0] = r2; f.b[2 * nj + 1][1] = r3;
    }
}

__global__ void __launch_bounds__(256, 2)
gemm_cp3(const __nv_bfloat16* __restrict__ A, int lda,
         const __nv_bfloat16* __restrict__ B, int ldb,
         float* __restrict__ C, int ldc, size_t zStride,
         int kLen, int epi,
         const float* __restrict__ bias,
         const float* __restrict__ resid)
{
    extern __shared__ char smem[];
    const uint32_t sbase = smem_u32(smem);
    const int tid  = threadIdx.x;
    const int lane = tid & 31;
    const int wid  = tid >> 5;
    const int wm   = wid >> 1;          // 0..3
    const int wn   = wid & 1;           // 0..1
    const int m0   = blockIdx.y * 128;
    const int n0   = blockIdx.x * 64;
    const int kOff = blockIdx.z * kLen;
    C += (size_t)blockIdx.z * zStride;

    // staging maps
    const int rowA = tid >> 1;          // 0..127, 4 chunks
    const int cgA  = (tid & 1) * 4;
    const int rkA  = rowA & 7;
    const int rowB = tid >> 2;          // 0..63, 2 chunks
    const int cgB  = (tid & 3) * 2;
    const int rkB  = rowB & 7;
    const __nv_bfloat16* aP = A + (size_t)(m0 + rowA) * lda + kOff;
    const __nv_bfloat16* bP = B + (size_t)(n0 + rowB) * ldb + kOff;
    const uint32_t rowABy = (uint32_t)rowA * 128u;
    const uint32_t rowBBy = (uint32_t)rowB * 128u;

    auto stage = [&](int st, int slot) {
        const uint32_t so = sbase + (uint32_t)slot * STG3;
        #pragma unroll
        for (int j = 0; j < 4; j++) {
            const int ch = cgA + j;
            CP16(so + rowABy + ((uint32_t)(ch ^ rkA) << 4), aP + st * 64 + ch * 8);
        }
        #pragma unroll
        for (int j = 0; j < 2; j++) {
            const int ch = cgB + j;
            CP16(so + 16384u + rowBBy + ((uint32_t)(ch ^ rkB) << 4),
                 bP + st * 64 + ch * 8);
        }
        CP_COMMIT();
    };

    // fragment row-byte offsets (within a stage)
    uint32_t aOff[2], bOff[2];
    #pragma unroll
    for (int mi = 0; mi < 2; mi++)
        aOff[mi] = (uint32_t)((wm * 32 + mi * 16 + (lane & 15)) * 128);
    #pragma unroll
    for (int nj = 0; nj < 2; nj++)
        bOff[nj] = (uint32_t)((wn * 32 + nj * 16 + (lane & 7) +
                               ((lane & 16) >> 1)) * 128) + 16384u;
    const uint32_t lk = (uint32_t)(lane & 7);

    float acc[2][4][4];
    #pragma unroll
    for (int i = 0; i < 2; i++)
        #pragma unroll
        for (int j = 0; j < 4; j++)
            #pragma unroll
            for (int q = 0; q < 4; q++) acc[i][j][q] = 0.f;

    const int iters = kLen >> 6;

    #pragma unroll
    for (int p = 0; p < 3; p++)
        if (p < iters) stage(p, p);

    Frag fr[2];
    for (int it = 0; it < iters; it++) {
        const int rem = iters - 1 - it;
        if (rem >= 2)      { CP_WAIT2(); }
        else if (rem == 1) { CP_WAIT1(); }
        else               { CP_WAIT0(); }
        __syncthreads();

        if (it + 3 < iters) stage(it + 3, (it + 3) & 3);

        const uint32_t sS = sbase + (uint32_t)(it & 3) * STG3;
        ld_frags(fr[0], sS, 0, aOff, bOff, (uint32_t)lane, lk);
        #pragma unroll
        for (int ks = 0; ks < 4; ks++) {
            const int cur = ks & 1;
            if (ks < 3)
                ld_frags(fr[cur ^ 1], sS, ks + 1, aOff, bOff, (uint32_t)lane, lk);
            #pragma unroll
            for (int mi = 0; mi < 2; mi++)
                #pragma unroll
                for (int ni = 0; ni < 4; ni++)
                    MMA_BF16(acc[mi][ni],
                             fr[cur].a[mi][0], fr[cur].a[mi][1],
                             fr[cur].a[mi][2], fr[cur].a[mi][3],
                             fr[cur].b[ni][0], fr[cur].b[ni][1]);
        }
    }

    // epilogue
    const int er = lane >> 2;
    const int ec = (lane & 3) * 2;
    __nv_bfloat16* Cb = (__nv_bfloat16*)C;
    #pragma unroll
    for (int mi = 0; mi < 2; mi++) {
        int gm = m0 + wm * 32 + mi * 16 + er;
        #pragma unroll
        for (int ni = 0; ni < 4; ni++) {
            int gn = n0 + wn * 32 + ni * 8 + ec;
            #pragma unroll
            for (int half = 0; half < 2; half++) {
                int gmm = gm + half * 8;
                float v0 = acc[mi][ni][half * 2];
                float v1 = acc[mi][ni][half * 2 + 1];
                if (epi == 4) {
                    *(uint32_t*)(Cb + (size_t)gmm * ldc + gn) = pack_bf2(v0, v1);
                } else if (epi == 1) {
                    v0 += bias[gn];
                    v1 += bias[gn + 1];
                    v0 = (v0 > 20.f) ? v0 : log1pf(__expf(v0));
                    v1 = (v1 > 20.f) ? v1 : log1pf(__expf(v1));
                    *(float2*)(C + (size_t)gmm * ldc + gn) = make_float2(v0, v1);
                } else if (epi == 2) {
                    const float2 r = *(const float2*)(resid + (size_t)gmm * ldc + gn);
                    *(float2*)(C + (size_t)gmm * ldc + gn) =
                        make_float2(v0 + r.x, v1 + r.y);
                } else {
                    *(float2*)(C + (size_t)gmm * ldc + gn) = make_float2(v0, v1);
                }
            }
        }
    }
}

// ---------------------------------------------------------------------------
__global__ void cvt_bf16_kernel(const float* __restrict__ in,
                                __nv_bfloat16* __restrict__ out, int n4)
{
    int i = blockIdx.x * blockDim.x + threadIdx.x;
    if (i >= n4) return;
    float4 v = *(const float4*)(in + (size_t)i * 4);
    *(uint2*)(out + (size_t)i * 4) =
        make_uint2(pack_bf2(v.x, v.y), pack_bf2(v.z, v.w));
}

__global__ void cvt_pad_x_kernel(const float* __restrict__ in,
                                 __nv_bfloat16* __restrict__ out)
{
    int i = blockIdx.x * blockDim.x + threadIdx.x;
    if (i >= 128 * DI / 4) return;
    int row = (i * 4) / DI;
    uint2 o;
    if (row < 96) {
        float4 v = *(const float4*)(in + (size_t)i * 4);
        o = make_uint2(pack_bf2(v.x, v.y), pack_bf2(v.z, v.w));
    } else {
        o = make_uint2(0u, 0u);
    }
    *(uint2*)(out + (size_t)i * 4) = o;
}

// ---------------------------------------------------------------------------
__global__ void rmsnorm_kernel(const float* __restrict__ x,
                               const float* __restrict__ w,
                               __nv_bfloat16* __restrict__ out)
{
    const int row = blockIdx.x;
    const int tid = threadIdx.x;
    const float* xr = x + (size_t)row * DM;

    float4 v = *(const float4*)(xr + tid * 4);
    float s = v.x * v.x + v.y * v.y + v.z * v.z + v.w * v.w;
    #pragma unroll
    for (int o = 16; o; o >>= 1) s += __shfl_xor_sync(0xffffffffu, s, o);

    __shared__ float sm[8];
    if ((tid & 31) == 0) sm[tid >> 5] = s;
    __syncthreads();
    float tot = sm[0] + sm[1] + sm[2] + sm[3] + sm[4] + sm[5] + sm[6] + sm[7];
    float scale = rsqrtf(tot * (1.f / DM) + 1e-6f);

    float4 wv = *(const float4*)(w + tid * 4);
    *(uint2*)(out + (size_t)row * DM + tid * 4) =
        make_uint2(pack_bf2(v.x * scale * wv.x, v.y * scale * wv.y),
                   pack_bf2(v.z * scale * wv.z, v.w * scale * wv.w));
}

// ---------------------------------------------------------------------------
__global__ void conv_silu_kernel(const __nv_bfloat16* __restrict__ xzb,
                                 const float* __restrict__ cw,
                                 const float* __restrict__ cb,
                                 __nv_bfloat16* __restrict__ ub)
{
    int gid = blockIdx.x * blockDim.x + threadIdx.x;
    if (gid >= R_TOT * DI) return;
    int d   = gid & (DI - 1);
    int row = gid >> 11;
    int t   = row & 1023;

    float acc = cb[d];
    #pragma unroll
    for (int j = 0; j < 4; j++) {
        int tt = t - 3 + j;
        if (tt >= 0)
            acc = fmaf(__bfloat162float(xzb[(size_t)(row - 3 + j) * (2 * DI) + d]),
                       cw[d * 4 + j], acc);
    }
    float s = acc / (1.f + __expf(-acc));
    ub[gid] = __float2bfloat16(s);
}

// ---------------------------------------------------------------------------
__global__ void xproj_reduce(const float* __restrict__ partial,
                             __nv_bfloat16* __restrict__ projb)
{
    int idx = blockIdx.x * blockDim.x + threadIdx.x;
    if (idx >= R_TOT * PSTR) return;
    float s = 0.f;
    #pragma unroll
    for (int p = 0; p < XS2; p++)
        s += partial[(size_t)p * R_TOT * PSTR + idx];
    projb[idx] = __float2bfloat16(s);
}

// ---------------------------------------------------------------------------
// Selective scan, ONE WAVE: 128 blocks x 512 threads, 32 channels/block.
// dt fp32; u/z/B/C bf16; padded smem (conflict-free stores); y bf16.
// ---------------------------------------------------------------------------
__global__ void __launch_bounds__(512)
scan_kernel(const float* __restrict__ dt,
            const __nv_bfloat16* __restrict__ ub,
            const __nv_bfloat16* __restrict__ pjb,
            const __nv_bfloat16* __restrict__ xzb,
            const float* __restrict__ A_log,
            const float* __restrict__ D_diag,
            __nv_bfloat16* __restrict__ yb)
{
    __shared__ float2 s_du[TCH][36];   // 288B row: +8 bank shift
    __shared__ float2 s_bc[TCH][18];   // 144B row: +4 bank shift
    __shared__ float  s_z [TCH][40];   // 160B row: 16B-aligned float4, +8 shift
    __shared__ float  s_y [TCH][40];

    const int tid  = threadIdx.x;
    const int n    = tid & 15;
    const int g    = tid >> 4;          // 0..31 channel
    const int dblk = blockIdx.x & 63;
    const int b    = blockIdx.x >> 6;
    const int d0   = dblk * 32;
    const int d    = d0 + g;
    const int bbase = b * 1024;

    const float Adn = -__expf(A_log[d * DST + n]);
    const float Dd  = D_diag[d];

    const int lr  = tid >> 3;           // 0..63 row (t)
    const int lc4 = (tid & 7) * 4;      // 4 channels

    float state = 0.f;
    for (int c = 0; c < 1024 / TCH; c++) {
        const int t0 = c * TCH;
        const size_t grow = (size_t)(bbase + t0 + lr);

        float4 dv = *(const float4*)(dt + grow * DI + d0 + lc4);
        uint2 uu = *(const uint2*)(ub + grow * DI + d0 + lc4);
        __nv_bfloat162 u01 = *(__nv_bfloat162*)&uu.x;
        __nv_bfloat162 u23 = *(__nv_bfloat162*)&uu.y;
        s_du[lr][lc4 + 0] = make_float2(dv.x, __bfloat162float(u01.x));
        s_du[lr][lc4 + 1] = make_float2(dv.y, __bfloat162float(u01.y));
        s_du[lr][lc4 + 2] = make_float2(dv.z, __bfloat162float(u23.x));
        s_du[lr][lc4 + 3] = make_float2(dv.w, __bfloat162float(u23.y));

        uint2 zz = *(const uint2*)(xzb + grow * (2 * DI) + DI + d0 + lc4);
        __nv_bfloat162 z01 = *(__nv_bfloat162*)&zz.x;
        __nv_bfloat162 z23 = *(__nv_bfloat162*)&zz.y;
        s_z[lr][lc4 + 0] = __bfloat162float(z01.x);
        s_z[lr][lc4 + 1] = __bfloat162float(z01.y);
        s_z[lr][lc4 + 2] = __bfloat162float(z23.x);
        s_z[lr][lc4 + 3] = __bfloat162float(z23.y);

        if (tid < 256) {                 // B/C shared across all 32 channels
            const int lrb = tid >> 2;    // 0..63
            const int lcb = (tid & 3) * 4;
            const size_t growb = (size_t)(bbase + t0 + lrb);
            uint2 bb = *(const uint2*)(pjb + growb * PSTR + 64 + lcb);
            uint2 cc = *(const uint2*)(pjb + growb * PSTR + 80 + lcb);
            __nv_bfloat162 b01 = *(__nv_bfloat162*)&bb.x;
            __nv_bfloat162 b23 = *(__nv_bfloat162*)&bb.y;
            __nv_bfloat162 c01 = *(__nv_bfloat162*)&cc.x;
            __nv_bfloat162 c23 = *(__nv_bfloat162*)&cc.y;
            s_bc[lrb][lcb + 0] = make_float2(__bfloat162float(b01.x), __bfloat162float(c01.x));
            s_bc[lrb][lcb + 1] = make_float2(__bfloat162float(b01.y), __bfloat162float(c01.y));
            s_bc[lrb][lcb + 2] = make_float2(__bfloat162float(b23.x), __bfloat162float(c23.x));
            s_bc[lrb][lcb + 3] = make_float2(__bfloat162float(b23.y), __bfloat162float(c23.y));
        }
        __syncthreads();

        #pragma unroll 8
        for (int t = 0; t < TCH; t++) {
            float2 du = s_du[t][g];
            float2 bc = s_bc[t][n];

            float dA = __expf(du.x * Adn);
            state = fmaf(dA, state, (du.x * du.y) * bc.x);

            float part = state * bc.y;
            part += __shfl_xor_sync(0xffffffffu, part, 1);
            part += __shfl_xor_sync(0xffffffffu, part, 2);
            part += __shfl_xor_sync(0xffffffffu, part, 4);
            part += __shfl_xor_sync(0xffffffffu, part, 8);

            if (n == 0) {
                float zv = s_z[t][g];
                float sz = zv / (1.f + __expf(-zv));
                s_y[t][g] = (part + Dd * du.y) * sz;
            }
        }
        __syncthreads();

        float4 v = *(const float4*)&s_y[lr][lc4];
        *(uint2*)(yb + grow * DI + d0 + lc4) =
            make_uint2(pack_bf2(v.x, v.y), pack_bf2(v.z, v.w));
    }
}

// ---------------------------------------------------------------------------
extern "C" void kernel_launch(void* const* d_in, const int* in_sizes, int n_in,
                              void* d_out, int out_size)
{
    const float* x          = (const float*)d_in[0];
    const float* norm_w     = (const float*)d_in[1];
    const float* in_proj_w  = (const float*)d_in[2];
    const float* conv_w     = (const float*)d_in[3];
    const float* conv_b     = (const float*)d_in[4];
    const float* x_proj_w   = (const float*)d_in[5];
    const float* dt_proj_w  = (const float*)d_in[6];
    const float* dt_proj_b  = (const float*)d_in[7];
    const float* A_log      = (const float*)d_in[8];
    const float* D_diag     = (const float*)d_in[9];
    const float* out_proj_w = (const float*)d_in[10];
    float* out = (float*)d_out;

    float *projp, *dtb;
    __nv_bfloat16 *xzb, *xnb, *ub, *pjb, *yb, *w1b, *w2b, *w3b, *wxb;
    cudaGetSymbolAddress((void**)&projp, g_projp);
    cudaGetSymbolAddress((void**)&dtb,   g_dt);
    cudaGetSymbolAddress((void**)&xzb,   g_xzb);
    cudaGetSymbolAddress((void**)&xnb,   g_xnb);
    cudaGetSymbolAddress((void**)&ub,    g_ub);
    cudaGetSymbolAddress((void**)&pjb,   g_pjb);
    cudaGetSymbolAddress((void**)&yb,    g_yb);
    cudaGetSymbolAddress((void**)&w1b,   g_w1b);
    cudaGetSymbolAddress((void**)&w2b,   g_w2b);
    cudaGetSymbolAddress((void**)&w3b,   g_w3b);
    cudaGetSymbolAddress((void**)&wxb,   g_wxb);

    cudaFuncSetAttribute(gemm_cp3, cudaFuncAttributeMaxDynamicSharedMemorySize,
                         SMEM_DYN3);

    // Launch order keeps in_proj as launch #4 (ncu capture comparability).
    cvt_bf16_kernel<<<(2 * DI * DM / 4 + 255) / 256, 256>>>(in_proj_w, w1b,
                                                            2 * DI * DM / 4);
    rmsnorm_kernel<<<R_TOT, 256>>>(x, norm_w, xnb);
    cvt_bf16_kernel<<<(DM * DI / 4 + 255) / 256, 256>>>(out_proj_w, w3b,
                                                        DM * DI / 4);
    // in_proj: 2048 x 4096 x 1024 -> xzb (bf16)
    gemm_cp3<<<dim3(64, 16, 1), 256, SMEM_DYN3>>>(
        xnb, DM, w1b, DM, (float*)xzb, 2 * DI, 0, DM, 4, nullptr, nullptr);
    conv_silu_kernel<<<(R_TOT * DI) / 256, 256>>>(xzb, conv_w, conv_b, ub);
    cvt_pad_x_kernel<<<(128 * DI / 4 + 255) / 256, 256>>>(x_proj_w, wxb);
    // x_proj split-K=8 (N padded to 128)
    gemm_cp3<<<dim3(2, 16, XS2), 256, SMEM_DYN3>>>(
        ub, DI, wxb, DI, projp, PSTR, (size_t)R_TOT * PSTR,
        DI / XS2, 0, nullptr, nullptr);
    xproj_reduce<<<(R_TOT * PSTR + 255) / 256, 256>>>(projp, pjb);
    cvt_bf16_kernel<<<(DI * DTR / 4 + 255) / 256, 256>>>(dt_proj_w, w2b,
                                                         DI * DTR / 4);
    // dt: softplus(proj[:, :64] @ dt_proj_w^T + b)
    gemm_cp3<<<dim3(32, 16, 1), 256, SMEM_DYN3>>>(
        pjb, PSTR, w2b, DTR, dtb, DI, 0, DTR, 1, dt_proj_b, nullptr);
    // selective scan, one wave
    scan_kernel<<<128, 512>>>(dtb, ub, pjb, xzb, A_log, D_diag, yb);
    // out_proj + residual
    gemm_cp3<<<dim3(16, 16, 1), 256, SMEM_DYN3>>>(
        yb, DI, w3b, DI, out, DM, 0, DI, 2, nullptr, x);
}

// round 16
// speedup vs baseline: 1.0364x; 1.0364x over previous
#include <cuda_runtime.h>
#include <cuda_bf16.h>
#include <cstdint>

// ---------------------------------------------------------------------------
// Mamba block. bf16 mma.sync GEMMs (r9 config) + merged cvt + 64-row-tile
// out_proj (staging FIXED: full 8-chunk rows). 9 kernel launches.
// ---------------------------------------------------------------------------

#define R_TOT   2048
#define DM      1024
#define DI      2048
#define DTR     64
#define DST     16
#define XS2     8
#define PSTR    128
#define TCH     64

// fp32 scratch
__device__ float g_projp [XS2 * R_TOT * PSTR];
__device__ float g_dt    [R_TOT * DI];
// bf16 scratch
__device__ __nv_bfloat16 g_xzb [R_TOT * 2 * DI];
__device__ __nv_bfloat16 g_xnb [R_TOT * DM];
__device__ __nv_bfloat16 g_ub  [R_TOT * DI];
__device__ __nv_bfloat16 g_pjb [R_TOT * PSTR];
__device__ __nv_bfloat16 g_yb  [R_TOT * DI];
__device__ __nv_bfloat16 g_w1b [2 * DI * DM];
__device__ __nv_bfloat16 g_w2b [DI * DTR];
__device__ __nv_bfloat16 g_w3b [DM * DI];
__device__ __nv_bfloat16 g_wxb [128 * DI];

// ---------------------------------------------------------------------------
__device__ __forceinline__ uint32_t smem_u32(const void* p) {
    uint32_t a;
    asm("{ .reg .u64 t; cvta.to.shared.u64 t, %1; cvt.u32.u64 %0, t; }"
        : "=r"(a) : "l"(p));
    return a;
}
__device__ __forceinline__ uint32_t pack_bf2(float x, float y) {
    __nv_bfloat162 h = __floats2bfloat162_rn(x, y);
    return *(uint32_t*)&h;
}

#define LDSM_X4(r0, r1, r2, r3, addr)                                          \
    asm volatile("ldmatrix.sync.aligned.m8n8.x4.shared.b16 {%0,%1,%2,%3}, [%4];" \
                 : "=r"(r0), "=r"(r1), "=r"(r2), "=r"(r3) : "r"(addr))

#define MMA_BF16(d, a0, a1, a2, a3, b0, b1)                                    \
    asm volatile("mma.sync.aligned.m16n8k16.row.col.f32.bf16.bf16.f32 "        \
                 "{%0,%1,%2,%3}, {%4,%5,%6,%7}, {%8,%9}, {%0,%1,%2,%3};"       \
                 : "+f"(d[0]), "+f"(d[1]), "+f"(d[2]), "+f"(d[3])              \
                 : "r"(a0), "r"(a1), "r"(a2), "r"(a3), "r"(b0), "r"(b1))

#define CP16(saddr, gptr)                                                      \
    asm volatile("cp.async.cg.shared.global [%0], [%1], 16;"                   \
                 :: "r"(saddr), "l"(gptr))
#define CP_COMMIT() asm volatile("cp.async.commit_group;" ::: "memory")
#define CP_WAIT0()  asm volatile("cp.async.wait_group 0;" ::: "memory")
#define CP_WAIT1()  asm volatile("cp.async.wait_group 1;" ::: "memory")

// Common epilogue: epi 0 fp32, 1 softplus(+bias), 2 +resid, 4 bf16
__device__ __forceinline__ void epi_store(
    float* C, int ldc, int gm, int gn, float v0, float v1, int epi,
    const float* bias, const float* resid)
{
    if (epi == 4) {
        *(uint32_t*)((__nv_bfloat16*)C + (size_t)gm * ldc + gn) = pack_bf2(v0, v1);
    } else if (epi == 1) {
        v0 += bias[gn];
        v1 += bias[gn + 1];
        v0 = (v0 > 20.f) ? v0 : log1pf(__expf(v0));
        v1 = (v1 > 20.f) ? v1 : log1pf(__expf(v1));
        *(float2*)(C + (size_t)gm * ldc + gn) = make_float2(v0, v1);
    } else if (epi == 2) {
        const float2 r = *(const float2*)(resid + (size_t)gm * ldc + gn);
        *(float2*)(C + (size_t)gm * ldc + gn) = make_float2(v0 + r.x, v1 + r.y);
    } else {
        *(float2*)(C + (size_t)gm * ldc + gn) = make_float2(v0, v1);
    }
}

// ---------------------------------------------------------------------------
// bf16 GEMM (r9 config): CTA 128x128, BK=64, 3-stage cp.async, 8 warps 2mx4n.
// ---------------------------------------------------------------------------
#define STG2      32768
#define SMEM_DYN2 (3 * STG2)

__global__ void __launch_bounds__(256, 2)
gemm_cp2(const __nv_bfloat16* __restrict__ A, int lda,
         const __nv_bfloat16* __restrict__ B, int ldb,
         float* __restrict__ C, int ldc, size_t zStride,
         int kLen, int epi,
         const float* __restrict__ bias,
         const float* __restrict__ resid)
{
    extern __shared__ char smem[];
    const uint32_t sbase = smem_u32(smem);
    const int tid  = threadIdx.x;
    const int lane = tid & 31;
    const int wid  = tid >> 5;
    const int wm   = wid >> 2;
    const int wn   = wid & 3;
    const int m0   = blockIdx.y * 128;
    const int n0   = blockIdx.x * 128;
    const int kOff = blockIdx.z * kLen;
    C += (size_t)blockIdx.z * zStride;

    const int row  = tid >> 1;
    const int cgrp = (tid & 1) * 4;
    const int rk   = row & 7;
    const __nv_bfloat16* aP = A + (size_t)(m0 + row) * lda + kOff;
    const __nv_bfloat16* bP = B + (size_t)(n0 + row) * ldb + kOff;
    const uint32_t rowB = (uint32_t)row * 128u;

    uint32_t aRowOff[4], bRowOff[2];
    #pragma unroll
    for (int mi = 0; mi < 4; mi++)
        aRowOff[mi] = (uint32_t)((wm * 64 + mi * 16 + (lane & 15)) * 128);
    #pragma unroll
    for (int nj = 0; nj < 2; nj++)
        bRowOff[nj] = (uint32_t)((wn * 32 + nj * 16 + (lane & 7) +
                                  ((lane & 16) >> 1)) * 128) + 16384u;
    const uint32_t lk = (uint32_t)(lane & 7);

    float acc[4][4][4];
    #pragma unroll
    for (int i = 0; i < 4; i++)
        #pragma unroll
        for (int j = 0; j < 4; j++)
            #pragma unroll
            for (int q = 0; q < 4; q++) acc[i][j][q] = 0.f;

    const int iters = kLen >> 6;

    #pragma unroll
    for (int p = 0; p < 2; p++) {
        if (p < iters) {
            const uint32_t so = sbase + (uint32_t)p * STG2;
            #pragma unroll
            for (int j = 0; j < 4; j++) {
                const int ch = cgrp + j;
                const uint32_t sw = (uint32_t)(ch ^ rk) << 4;
                CP16(so + rowB + sw,          aP + p * 64 + ch * 8);
                CP16(so + 16384u + rowB + sw, bP + p * 64 + ch * 8);
            }
            CP_COMMIT();
        }
    }

    int slot = 0, nslot = (iters >= 3) ? 2 : 0;
    for (int it = 0; it < iters; it++) {
        if (it == iters - 1) { CP_WAIT0(); } else { CP_WAIT1(); }
        __syncthreads();

        if (it + 2 < iters) {
            const int st = it + 2;
            const uint32_t so = sbase + (uint32_t)nslot * STG2;
            #pragma unroll
            for (int j = 0; j < 4; j++) {
                const int ch = cgrp + j;
                const uint32_t sw = (uint32_t)(ch ^ rk) << 4;
                CP16(so + rowB + sw,          aP + st * 64 + ch * 8);
                CP16(so + 16384u + rowB + sw, bP + st * 64 + ch * 8);
            }
            CP_COMMIT();
            nslot = (nslot == 2) ? 0 : nslot + 1;
        }

        const uint32_t sS = sbase + (uint32_t)slot * STG2;
        #pragma unroll
        for (int ks = 0; ks < 4; ks++) {
            const uint32_t swA = (uint32_t)((ks * 2 + (lane >> 4)) ^ lk) << 4;
            const uint32_t swB = (uint32_t)((ks * 2 + ((lane >> 3) & 1)) ^ lk) << 4;
            uint32_t a[4][4];
            #pragma unroll
            for (int mi = 0; mi < 4; mi++)
                LDSM_X4(a[mi][0], a[mi][1], a[mi][2], a[mi][3],
                        sS + aRowOff[mi] + swA);
            uint32_t b[4][2];
            #pragma unroll
            for (int nj = 0; nj < 2; nj++) {
                uint32_t r0, r1, r2, r3;
                LDSM_X4(r0, r1, r2, r3, sS + bRowOff[nj] + swB);
                b[2 * nj][0] = r0; b[2 * nj][1] = r1;
                b[2 * nj + 1][0] = r2; b[2 * nj + 1][1] = r3;
            }
            #pragma unroll
            for (int mi = 0; mi < 4; mi++)
                #pragma unroll
                for (int ni = 0; ni < 4; ni++)
                    MMA_BF16(acc[mi][ni], a[mi][0], a[mi][1], a[mi][2], a[mi][3],
                             b[ni][0], b[ni][1]);
        }
        slot = (slot == 2) ? 0 : slot + 1;
    }

    const int er = lane >> 2;
    const int ec = (lane & 3) * 2;
    #pragma unroll
    for (int mi = 0; mi < 4; mi++) {
        int gm = m0 + wm * 64 + mi * 16 + er;
        #pragma unroll
        for (int ni = 0; ni < 4; ni++) {
            int gn = n0 + wn * 32 + ni * 8 + ec;
            #pragma unroll
            for (int half = 0; half < 2; half++)
                epi_store(C, ldc, gm + half * 8, gn,
                          acc[mi][ni][half * 2], acc[mi][ni][half * 2 + 1],
                          epi, bias, resid);
        }
    }
}

// ---------------------------------------------------------------------------
// bf16 GEMM, 64x128 CTA tile (out_proj). 8 warps 2m x 4n, warp 32x32, BK=64.
// Staging FIX: A rows get all 8 chunks (2/thread), B rows all 8 (4/thread).
// ---------------------------------------------------------------------------
#define STG64      24576                  // A 8K + B 16K
#define SMEM_DYN64 (3 * STG64)

__global__ void __launch_bounds__(256, 2)
gemm64(const __nv_bfloat16* __restrict__ A, int lda,
       const __nv_bfloat16* __restrict__ B, int ldb,
       float* __restrict__ C, int ldc,
       int kLen, int epi,
       const float* __restrict__ bias,
       const float* __restrict__ resid)
{
    extern __shared__ char smem[];
    const uint32_t sbase = smem_u32(smem);
    const int tid  = threadIdx.x;
    const int lane = tid & 31;
    const int wid  = tid >> 5;
    const int wm   = wid & 1;
    const int wn   = wid >> 1;
    const int m0   = blockIdx.y * 64;
    const int n0   = blockIdx.x * 128;

    // staging (FIXED): A 64 rows x 8 chunks -> 2 chunks/thread;
    //                  B 128 rows x 8 chunks -> 4 chunks/thread
    const int rowA = tid >> 2;           // 0..63
    const int cgA  = (tid & 3) * 2;      // chunks {cgA, cgA+1}
    const int rkA  = rowA & 7;
    const int rowB = tid >> 1;           // 0..127
    const int cgB  = (tid & 1) * 4;      // chunks {cgB..cgB+3}
    const int rkB  = rowB & 7;
    const __nv_bfloat16* aP = A + (size_t)(m0 + rowA) * lda;
    const __nv_bfloat16* bP = B + (size_t)(n0 + rowB) * ldb;
    const uint32_t rowABy = (uint32_t)rowA * 128u;
    const uint32_t rowBBy = (uint32_t)rowB * 128u;

    auto stage = [&](int st, int slot) {
        const uint32_t so = sbase + (uint32_t)slot * STG64;
        #pragma unroll
        for (int j = 0; j < 2; j++) {
            const int ch = cgA + j;
            CP16(so + rowABy + ((uint32_t)(ch ^ rkA) << 4), aP + st * 64 + ch * 8);
        }
        #pragma unroll
        for (int j = 0; j < 4; j++) {
            const int ch = cgB + j;
            CP16(so + 8192u + rowBBy + ((uint32_t)(ch ^ rkB) << 4),
                 bP + st * 64 + ch * 8);
        }
        CP_COMMIT();
    };

    uint32_t aOff[2], bOff[2];
    #pragma unroll
    for (int mi = 0; mi < 2; mi++)
        aOff[mi] = (uint32_t)((wm * 32 + mi * 16 + (lane & 15)) * 128);
    #pragma unroll
    for (int nj = 0; nj < 2; nj++)
        bOff[nj] = (uint32_t)((wn * 32 + nj * 16 + (lane & 7) +
                               ((lane & 16) >> 1)) * 128) + 8192u;
    const uint32_t lk = (uint32_t)(lane & 7);

    float acc[2][4][4];
    #pragma unroll
    for (int i = 0; i < 2; i++)
        #pragma unroll
        for (int j = 0; j < 4; j++)
            #pragma unroll
            for (int q = 0; q < 4; q++) acc[i][j][q] = 0.f;

    const int iters = kLen >> 6;

    #pragma unroll
    for (int p = 0; p < 2; p++)
        if (p < iters) stage(p, p);

    int slot = 0, nslot = (iters >= 3) ? 2 : 0;
    for (int it = 0; it < iters; it++) {
        if (it == iters - 1) { CP_WAIT0(); } else { CP_WAIT1(); }
        __syncthreads();

        if (it + 2 < iters) {
            stage(it + 2, nslot);
            nslot = (nslot == 2) ? 0 : nslot + 1;
        }

        const uint32_t sS = sbase + (uint32_t)slot * STG64;
        #pragma unroll
        for (int ks = 0; ks < 4; ks++) {
            const uint32_t swA = (uint32_t)((ks * 2 + (lane >> 4)) ^ lk) << 4;
            const uint32_t swB = (uint32_t)((ks * 2 + ((lane >> 3) & 1)) ^ lk) << 4;
            uint32_t a[2][4];
            #pragma unroll
            for (int mi = 0; mi < 2; mi++)
                LDSM_X4(a[mi][0], a[mi][1], a[mi][2], a[mi][3],
                        sS + aOff[mi] + swA);
            uint32_t b[4][2];
            #pragma unroll
            for (int nj = 0; nj < 2; nj++) {
                uint32_t r0, r1, r2, r3;
                LDSM_X4(r0, r1, r2, r3, sS + bOff[nj] + swB);
                b[2 * nj][0] = r0; b[2 * nj][1] = r1;
                b[2 * nj + 1][0] = r2; b[2 * nj + 1][1] = r3;
            }
            #pragma unroll
            for (int mi = 0; mi < 2; mi++)
                #pragma unroll
                for (int ni = 0; ni < 4; ni++)
                    MMA_BF16(acc[mi][ni], a[mi][0], a[mi][1], a[mi][2], a[mi][3],
                             b[ni][0], b[ni][1]);
        }
        slot = (slot == 2) ? 0 : slot + 1;
    }

    const int er = lane >> 2;
    const int ec = (lane & 3) * 2;
    #pragma unroll
    for (int mi = 0; mi < 2; mi++) {
        int gm = m0 + wm * 32 + mi * 16 + er;
        #pragma unroll
        for (int ni = 0; ni < 4; ni++) {
            int gn = n0 + wn * 32 + ni * 8 + ec;
            #pragma unroll
            for (int half = 0; half < 2; half++)
                epi_store(C, ldc, gm + half * 8, gn,
                          acc[mi][ni][half * 2], acc[mi][ni][half * 2 + 1],
                          epi, bias, resid);
        }
    }
}

// ---------------------------------------------------------------------------
// Merged weight conversion: w1 | w3 | w2 | wx(pad to 128 rows)
// ---------------------------------------------------------------------------
#define N1Q (2 * DI * DM / 4)
#define N3Q (DM * DI / 4)
#define N2Q (DI * DTR / 4)
#define NXQ (128 * DI / 4)

__global__ void cvt_all_kernel(const float* __restrict__ w1,
                               const float* __restrict__ w3,
                               const float* __restrict__ w2,
                               const float* __restrict__ wx,
                               __nv_bfloat16* __restrict__ o1,
                               __nv_bfloat16* __restrict__ o3,
                               __nv_bfloat16* __restrict__ o2,
                               __nv_bfloat16* __restrict__ ox)
{
    int i = blockIdx.x * blockDim.x + threadIdx.x;
    const float* src;
    __nv_bfloat16* dst;
    int j = i;
    if (i < N1Q)                        { src = w1; dst = o1; }
    else if ((j = i - N1Q) < N3Q)       { src = w3; dst = o3; }
    else if ((j = i - N1Q - N3Q) < N2Q) { src = w2; dst = o2; }
    else {
        j = i - N1Q - N3Q - N2Q;
        if (j >= NXQ) return;
        int rowx = (j * 4) / DI;
        uint2 o;
        if (rowx < 96) {
            float4 v = *(const float4*)(wx + (size_t)j * 4);
            o = make_uint2(pack_bf2(v.x, v.y), pack_bf2(v.z, v.w));
        } else {
            o = make_uint2(0u, 0u);
        }
        *(uint2*)(ox + (size_t)j * 4) = o;
        return;
    }
    float4 v = *(const float4*)(src + (size_t)j * 4);
    *(uint2*)(dst + (size_t)j * 4) =
        make_uint2(pack_bf2(v.x, v.y), pack_bf2(v.z, v.w));
}

// ---------------------------------------------------------------------------
__global__ void rmsnorm_kernel(const float* __restrict__ x,
                               const float* __restrict__ w,
                               __nv_bfloat16* __restrict__ out)
{
    const int row = blockIdx.x;
    const int tid = threadIdx.x;
    const float* xr = x + (size_t)row * DM;

    float4 v = *(const float4*)(xr + tid * 4);
    float s = v.x * v.x + v.y * v.y + v.z * v.z + v.w * v.w;
    #pragma unroll
    for (int o = 16; o; o >>= 1) s += __shfl_xor_sync(0xffffffffu, s, o);

    __shared__ float sm[8];
    if ((tid & 31) == 0) sm[tid >> 5] = s;
    __syncthreads();
    float tot = sm[0] + sm[1] + sm[2] + sm[3] + sm[4] + sm[5] + sm[6] + sm[7];
    float scale = rsqrtf(tot * (1.f / DM) + 1e-6f);

    float4 wv = *(const float4*)(w + tid * 4);
    *(uint2*)(out + (size_t)row * DM + tid * 4) =
        make_uint2(pack_bf2(v.x * scale * wv.x, v.y * scale * wv.y),
                   pack_bf2(v.z * scale * wv.z, v.w * scale * wv.w));
}

// ---------------------------------------------------------------------------
__global__ void conv_silu_kernel(const __nv_bfloat16* __restrict__ xzb,
                                 const float* __restrict__ cw,
                                 const float* __restrict__ cb,
                                 __nv_bfloat16* __restrict__ ub)
{
    int gid = blockIdx.x * blockDim.x + threadIdx.x;
    if (gid >= R_TOT * DI) return;
    int d   = gid & (DI - 1);
    int row = gid >> 11;
    int t   = row & 1023;

    float acc = cb[d];
    #pragma unroll
    for (int j = 0; j < 4; j++) {
        int tt = t - 3 + j;
        if (tt >= 0)
            acc = fmaf(__bfloat162float(xzb[(size_t)(row - 3 + j) * (2 * DI) + d]),
                       cw[d * 4 + j], acc);
    }
    float s = acc / (1.f + __expf(-acc));
    ub[gid] = __float2bfloat16(s);
}

// ---------------------------------------------------------------------------
__global__ void xproj_reduce(const float* __restrict__ partial,
                             __nv_bfloat16* __restrict__ projb)
{
    int idx = blockIdx.x * blockDim.x + threadIdx.x;
    if (idx >= R_TOT * PSTR) return;
    float s = 0.f;
    #pragma unroll
    for (int p = 0; p < XS2; p++)
        s += partial[(size_t)p * R_TOT * PSTR + idx];
    projb[idx] = __float2bfloat16(s);
}

// ---------------------------------------------------------------------------
// Selective scan (r9 version)
// ---------------------------------------------------------------------------
__global__ void __launch_bounds__(256)
scan_kernel(const float* __restrict__ dt,
            const __nv_bfloat16* __restrict__ ub,
            const __nv_bfloat16* __restrict__ pjb,
            const __nv_bfloat16* __restrict__ xzb,
            const float* __restrict__ A_log,
            const float* __restrict__ D_diag,
            __nv_bfloat16* __restrict__ yb)
{
    __shared__ float2 s_du[TCH][16];
    __shared__ float2 s_bc[TCH][16];
    __shared__ float  s_z [TCH][16];
    __shared__ float  s_y [TCH][16];

    const int tid  = threadIdx.x;
    const int n    = tid & 15;
    const int g    = tid >> 4;
    const int dblk = blockIdx.x & 127;
    const int b    = blockIdx.x >> 7;
    const int d0   = dblk * 16;
    const int d    = d0 + g;
    const int bbase = b * 1024;

    const float Adn = -__expf(A_log[d * DST + n]);
    const float Dd  = D_diag[d];

    const int lr  = tid >> 2;
    const int lc4 = (tid & 3) * 4;

    float state = 0.f;
    for (int c = 0; c < 1024 / TCH; c++) {
        const int t0 = c * TCH;
        const size_t grow = (size_t)(bbase + t0 + lr);

        float4 dv = *(const float4*)(dt + grow * DI + d0 + lc4);
        uint2 uu = *(const uint2*)(ub + grow * DI + d0 + lc4);
        __nv_bfloat162 u01 = *(__nv_bfloat162*)&uu.x;
        __nv_bfloat162 u23 = *(__nv_bfloat162*)&uu.y;
        s_du[lr][lc4 + 0] = make_float2(dv.x, __bfloat162float(u01.x));
        s_du[lr][lc4 + 1] = make_float2(dv.y, __bfloat162float(u01.y));
        s_du[lr][lc4 + 2] = make_float2(dv.z, __bfloat162float(u23.x));
        s_du[lr][lc4 + 3] = make_float2(dv.w, __bfloat162float(u23.y));

        uint2 zz = *(const uint2*)(xzb + grow * (2 * DI) + DI + d0 + lc4);
        __nv_bfloat162 z01 = *(__nv_bfloat162*)&zz.x;
        __nv_bfloat162 z23 = *(__nv_bfloat162*)&zz.y;
        s_z[lr][lc4 + 0] = __bfloat162float(z01.x);
        s_z[lr][lc4 + 1] = __bfloat162float(z01.y);
        s_z[lr][lc4 + 2] = __bfloat162float(z23.x);
        s_z[lr][lc4 + 3] = __bfloat162float(z23.y);

        {
            uint2 bb = *(const uint2*)(pjb + grow * PSTR + 64 + lc4);
            uint2 cc = *(const uint2*)(pjb + grow * PSTR + 80 + lc4);
            __nv_bfloat162 b01 = *(__nv_bfloat162*)&bb.x;
            __nv_bfloat162 b23 = *(__nv_bfloat162*)&bb.y;
            __nv_bfloat162 c01 = *(__nv_bfloat162*)&cc.x;
            __nv_bfloat162 c23 = *(__nv_bfloat162*)&cc.y;
            s_bc[lr][lc4 + 0] = make_float2(__bfloat162float(b01.x), __bfloat162float(c01.x));
            s_bc[lr][lc4 + 1] = make_float2(__bfloat162float(b01.y), __bfloat162float(c01.y));
            s_bc[lr][lc4 + 2] = make_float2(__bfloat162float(b23.x), __bfloat162float(c23.x));
            s_bc[lr][lc4 + 3] = make_float2(__bfloat162float(b23.y), __bfloat162float(c23.y));
        }
        __syncthreads();

        #pragma unroll 8
        for (int t = 0; t < TCH; t++) {
            float2 du = s_du[t][g];
            float2 bc = s_bc[t][n];

            float dA = __expf(du.x * Adn);
            state = fmaf(dA, state, (du.x * du.y) * bc.x);

            float part = state * bc.y;
            part += __shfl_xor_sync(0xffffffffu, part, 1);
            part += __shfl_xor_sync(0xffffffffu, part, 2);
            part += __shfl_xor_sync(0xffffffffu, part, 4);
            part += __shfl_xor_sync(0xffffffffu, part, 8);

            if (n == 0) {
                float zv = s_z[t][g];
                float sz = zv / (1.f + __expf(-zv));
                s_y[t][g] = (part + Dd * du.y) * sz;
            }
        }
        __syncthreads();

        float4 v = *(const float4*)&s_y[lr][lc4];
        *(uint2*)(yb + grow * DI + d0 + lc4) =
            make_uint2(pack_bf2(v.x, v.y), pack_bf2(v.z, v.w));
    }
}

// ---------------------------------------------------------------------------
extern "C" void kernel_launch(void* const* d_in, const int* in_sizes, int n_in,
                              void* d_out, int out_size)
{
    const float* x          = (const float*)d_in[0];
    const float* norm_w     = (const float*)d_in[1];
    const float* in_proj_w  = (const float*)d_in[2];
    const float* conv_w     = (const float*)d_in[3];
    const float* conv_b     = (const float*)d_in[4];
    const float* x_proj_w   = (const float*)d_in[5];
    const float* dt_proj_w  = (const float*)d_in[6];
    const float* dt_proj_b  = (const float*)d_in[7];
    const float* A_log      = (const float*)d_in[8];
    const float* D_diag     = (const float*)d_in[9];
    const float* out_proj_w = (const float*)d_in[10];
    float* out = (float*)d_out;

    float *projp, *dtb;
    __nv_bfloat16 *xzb, *xnb, *ub, *pjb, *yb, *w1b, *w2b, *w3b, *wxb;
    cudaGetSymbolAddress((void**)&projp, g_projp);
    cudaGetSymbolAddress((void**)&dtb,   g_dt);
    cudaGetSymbolAddress((void**)&xzb,   g_xzb);
    cudaGetSymbolAddress((void**)&xnb,   g_xnb);
    cudaGetSymbolAddress((void**)&ub,    g_ub);
    cudaGetSymbolAddress((void**)&pjb,   g_pjb);
    cudaGetSymbolAddress((void**)&yb,    g_yb);
    cudaGetSymbolAddress((void**)&w1b,   g_w1b);
    cudaGetSymbolAddress((void**)&w2b,   g_w2b);
    cudaGetSymbolAddress((void**)&w3b,   g_w3b);
    cudaGetSymbolAddress((void**)&wxb,   g_wxb);

    cudaFuncSetAttribute(gemm_cp2, cudaFuncAttributeMaxDynamicSharedMemorySize,
                         SMEM_DYN2);
    cudaFuncSetAttribute(gemm64, cudaFuncAttributeMaxDynamicSharedMemorySize,
                         SMEM_DYN64);

    const int NTOT = N1Q + N3Q + N2Q + NXQ;

    // 1) all weight conversions
    cvt_all_kernel<<<(NTOT + 255) / 256, 256>>>(in_proj_w, out_proj_w,
                                                dt_proj_w, x_proj_w,
                                                w1b, w3b, w2b, wxb);
    // 2) RMSNorm -> bf16
    rmsnorm_kernel<<<R_TOT, 256>>>(x, norm_w, xnb);
    // 3) in_proj: 2048 x 4096 x 1024 -> xzb (bf16)
    gemm_cp2<<<dim3(32, 16, 1), 256, SMEM_DYN2>>>(
        xnb, DM, w1b, DM, (float*)xzb, 2 * DI, 0, DM, 4, nullptr, nullptr);
    // 4) conv + silu -> ub
    conv_silu_kernel<<<(R_TOT * DI) / 256, 256>>>(xzb, conv_w, conv_b, ub);
    // 5) x_proj split-K=8 (N padded 128) -> fp32 partials
    gemm_cp2<<<dim3(1, 16, XS2), 256, SMEM_DYN2>>>(
        ub, DI, wxb, DI, projp, PSTR, (size_t)R_TOT * PSTR,
        DI / XS2, 0, nullptr, nullptr);
    // 6) reduce -> pjb (bf16)
    xproj_reduce<<<(R_TOT * PSTR + 255) / 256, 256>>>(projp, pjb);
    // 7) dt: softplus(proj[:, :64] @ dt_proj_w^T + b) -> fp32
    gemm_cp2<<<dim3(16, 16, 1), 256, SMEM_DYN2>>>(
        pjb, PSTR, w2b, DTR, dtb, DI, 0, DTR, 1, dt_proj_b, nullptr);
    // 8) selective scan -> yb (bf16)
    scan_kernel<<<256, 256>>>(dtb, ub, pjb, xzb, A_log, D_diag, yb);
    // 9) out_proj + residual (64-row tiles, 256 CTAs)
    gemm64<<<dim3(8, 32), 256, SMEM_DYN64>>>(
        yb, DI, w3b, DI, out, DM, DI, 2, nullptr, x);
}

// round 17
// speedup vs baseline: 1.0434x; 1.0068x over previous
#include <cuda_runtime.h>
#include <cuda_bf16.h>
#include <cstdint>

// ---------------------------------------------------------------------------
// Mamba block. r16 + fast softplus epilogue + one-wave scan (128x512).
// ---------------------------------------------------------------------------

#define R_TOT   2048
#define DM      1024
#define DI      2048
#define DTR     64
#define DST     16
#define XS2     8
#define PSTR    128
#define TCH     64

// fp32 scratch
__device__ float g_projp [XS2 * R_TOT * PSTR];
__device__ float g_dt    [R_TOT * DI];
// bf16 scratch
__device__ __nv_bfloat16 g_xzb [R_TOT * 2 * DI];
__device__ __nv_bfloat16 g_xnb [R_TOT * DM];
__device__ __nv_bfloat16 g_ub  [R_TOT * DI];
__device__ __nv_bfloat16 g_pjb [R_TOT * PSTR];
__device__ __nv_bfloat16 g_yb  [R_TOT * DI];
__device__ __nv_bfloat16 g_w1b [2 * DI * DM];
__device__ __nv_bfloat16 g_w2b [DI * DTR];
__device__ __nv_bfloat16 g_w3b [DM * DI];
__device__ __nv_bfloat16 g_wxb [128 * DI];

// ---------------------------------------------------------------------------
__device__ __forceinline__ uint32_t smem_u32(const void* p) {
    uint32_t a;
    asm("{ .reg .u64 t; cvta.to.shared.u64 t, %1; cvt.u32.u64 %0, t; }"
        : "=r"(a) : "l"(p));
    return a;
}
__device__ __forceinline__ uint32_t pack_bf2(float x, float y) {
    __nv_bfloat162 h = __floats2bfloat162_rn(x, y);
    return *(uint32_t*)&h;
}
__device__ __forceinline__ float softplus_fast(float v) {
    return (v > 15.f) ? v : __logf(1.f + __expf(v));
}

#define LDSM_X4(r0, r1, r2, r3, addr)                                          \
    asm volatile("ldmatrix.sync.aligned.m8n8.x4.shared.b16 {%0,%1,%2,%3}, [%4];" \
                 : "=r"(r0), "=r"(r1), "=r"(r2), "=r"(r3) : "r"(addr))

#define MMA_BF16(d, a0, a1, a2, a3, b0, b1)                                    \
    asm volatile("mma.sync.aligned.m16n8k16.row.col.f32.bf16.bf16.f32 "        \
                 "{%0,%1,%2,%3}, {%4,%5,%6,%7}, {%8,%9}, {%0,%1,%2,%3};"       \
                 : "+f"(d[0]), "+f"(d[1]), "+f"(d[2]), "+f"(d[3])              \
                 : "r"(a0), "r"(a1), "r"(a2), "r"(a3), "r"(b0), "r"(b1))

#define CP16(saddr, gptr)                                                      \
    asm volatile("cp.async.cg.shared.global [%0], [%1], 16;"                   \
                 :: "r"(saddr), "l"(gptr))
#define CP_COMMIT() asm volatile("cp.async.commit_group;" ::: "memory")
#define CP_WAIT0()  asm volatile("cp.async.wait_group 0;" ::: "memory")
#define CP_WAIT1()  asm volatile("cp.async.wait_group 1;" ::: "memory")

// epi: 0 fp32, 1 softplus(+bias), 2 +resid, 4 bf16
__device__ __forceinline__ void epi_store(
    float* C, int ldc, int gm, int gn, float v0, float v1, int epi,
    const float* bias, const float* resid)
{
    if (epi == 4) {
        *(uint32_t*)((__nv_bfloat16*)C + (size_t)gm * ldc + gn) = pack_bf2(v0, v1);
    } else if (epi == 1) {
        v0 = softplus_fast(v0 + bias[gn]);
        v1 = softplus_fast(v1 + bias[gn + 1]);
        *(float2*)(C + (size_t)gm * ldc + gn) = make_float2(v0, v1);
    } else if (epi == 2) {
        const float2 r = *(const float2*)(resid + (size_t)gm * ldc + gn);
        *(float2*)(C + (size_t)gm * ldc + gn) = make_float2(v0 + r.x, v1 + r.y);
    } else {
        *(float2*)(C + (size_t)gm * ldc + gn) = make_float2(v0, v1);
    }
}

// ---------------------------------------------------------------------------
// bf16 GEMM (r9 config): CTA 128x128, BK=64, 3-stage cp.async, 8 warps 2mx4n.
// ---------------------------------------------------------------------------
#define STG2      32768
#define SMEM_DYN2 (3 * STG2)

__global__ void __launch_bounds__(256, 2)
gemm_cp2(const __nv_bfloat16* __restrict__ A, int lda,
         const __nv_bfloat16* __restrict__ B, int ldb,
         float* __restrict__ C, int ldc, size_t zStride,
         int kLen, int epi,
         const float* __restrict__ bias,
         const float* __restrict__ resid)
{
    extern __shared__ char smem[];
    const uint32_t sbase = smem_u32(smem);
    const int tid  = threadIdx.x;
    const int lane = tid & 31;
    const int wid  = tid >> 5;
    const int wm   = wid >> 2;
    const int wn   = wid & 3;
    const int m0   = blockIdx.y * 128;
    const int n0   = blockIdx.x * 128;
    const int kOff = blockIdx.z * kLen;
    C += (size_t)blockIdx.z * zStride;

    const int row  = tid >> 1;
    const int cgrp = (tid & 1) * 4;
    const int rk   = row & 7;
    const __nv_bfloat16* aP = A + (size_t)(m0 + row) * lda + kOff;
    const __nv_bfloat16* bP = B + (size_t)(n0 + row) * ldb + kOff;
    const uint32_t rowB = (uint32_t)row * 128u;

    uint32_t aRowOff[4], bRowOff[2];
    #pragma unroll
    for (int mi = 0; mi < 4; mi++)
        aRowOff[mi] = (uint32_t)((wm * 64 + mi * 16 + (lane & 15)) * 128);
    #pragma unroll
    for (int nj = 0; nj < 2; nj++)
        bRowOff[nj] = (uint32_t)((wn * 32 + nj * 16 + (lane & 7) +
                                  ((lane & 16) >> 1)) * 128) + 16384u;
    const uint32_t lk = (uint32_t)(lane & 7);

    float acc[4][4][4];
    #pragma unroll
    for (int i = 0; i < 4; i++)
        #pragma unroll
        for (int j = 0; j < 4; j++)
            #pragma unroll
            for (int q = 0; q < 4; q++) acc[i][j][q] = 0.f;

    const int iters = kLen >> 6;

    #pragma unroll
    for (int p = 0; p < 2; p++) {
        if (p < iters) {
            const uint32_t so = sbase + (uint32_t)p * STG2;
            #pragma unroll
            for (int j = 0; j < 4; j++) {
                const int ch = cgrp + j;
                const uint32_t sw = (uint32_t)(ch ^ rk) << 4;
                CP16(so + rowB + sw,          aP + p * 64 + ch * 8);
                CP16(so + 16384u + rowB + sw, bP + p * 64 + ch * 8);
            }
            CP_COMMIT();
        }
    }

    int slot = 0, nslot = (iters >= 3) ? 2 : 0;
    for (int it = 0; it < iters; it++) {
        if (it == iters - 1) { CP_WAIT0(); } else { CP_WAIT1(); }
        __syncthreads();

        if (it + 2 < iters) {
            const int st = it + 2;
            const uint32_t so = sbase + (uint32_t)nslot * STG2;
            #pragma unroll
            for (int j = 0; j < 4; j++) {
                const int ch = cgrp + j;
                const uint32_t sw = (uint32_t)(ch ^ rk) << 4;
                CP16(so + rowB + sw,          aP + st * 64 + ch * 8);
                CP16(so + 16384u + rowB + sw, bP + st * 64 + ch * 8);
            }
            CP_COMMIT();
            nslot = (nslot == 2) ? 0 : nslot + 1;
        }

        const uint32_t sS = sbase + (uint32_t)slot * STG2;
        #pragma unroll
        for (int ks = 0; ks < 4; ks++) {
            const uint32_t swA = (uint32_t)((ks * 2 + (lane >> 4)) ^ lk) << 4;
            const uint32_t swB = (uint32_t)((ks * 2 + ((lane >> 3) & 1)) ^ lk) << 4;
            uint32_t a[4][4];
            #pragma unroll
            for (int mi = 0; mi < 4; mi++)
                LDSM_X4(a[mi][0], a[mi][1], a[mi][2], a[mi][3],
                        sS + aRowOff[mi] + swA);
            uint32_t b[4][2];
            #pragma unroll
            for (int nj = 0; nj < 2; nj++) {
                uint32_t r0, r1, r2, r3;
                LDSM_X4(r0, r1, r2, r3, sS + bRowOff[nj] + swB);
                b[2 * nj][0] = r0; b[2 * nj][1] = r1;
                b[2 * nj + 1][0] = r2; b[2 * nj + 1][1] = r3;
            }
            #pragma unroll
            for (int mi = 0; mi < 4; mi++)
                #pragma unroll
                for (int ni = 0; ni < 4; ni++)
                    MMA_BF16(acc[mi][ni], a[mi][0], a[mi][1], a[mi][2], a[mi][3],
                             b[ni][0], b[ni][1]);
        }
        slot = (slot == 2) ? 0 : slot + 1;
    }

    const int er = lane >> 2;
    const int ec = (lane & 3) * 2;
    #pragma unroll
    for (int mi = 0; mi < 4; mi++) {
        int gm = m0 + wm * 64 + mi * 16 + er;
        #pragma unroll
        for (int ni = 0; ni < 4; ni++) {
            int gn = n0 + wn * 32 + ni * 8 + ec;
            #pragma unroll
            for (int half = 0; half < 2; half++)
                epi_store(C, ldc, gm + half * 8, gn,
                          acc[mi][ni][half * 2], acc[mi][ni][half * 2 + 1],
                          epi, bias, resid);
        }
    }
}

// ---------------------------------------------------------------------------
// bf16 GEMM, 64x128 CTA tile (out_proj), fixed staging.
// ---------------------------------------------------------------------------
#define STG64      24576
#define SMEM_DYN64 (3 * STG64)

__global__ void __launch_bounds__(256, 2)
gemm64(const __nv_bfloat16* __restrict__ A, int lda,
       const __nv_bfloat16* __restrict__ B, int ldb,
       float* __restrict__ C, int ldc,
       int kLen, int epi,
       const float* __restrict__ bias,
       const float* __restrict__ resid)
{
    extern __shared__ char smem[];
    const uint32_t sbase = smem_u32(smem);
    const int tid  = threadIdx.x;
    const int lane = tid & 31;
    const int wid  = tid >> 5;
    const int wm   = wid & 1;
    const int wn   = wid >> 1;
    const int m0   = blockIdx.y * 64;
    const int n0   = blockIdx.x * 128;

    const int rowA = tid >> 2;
    const int cgA  = (tid & 3) * 2;
    const int rkA  = rowA & 7;
    const int rowB = tid >> 1;
    const int cgB  = (tid & 1) * 4;
    const int rkB  = rowB & 7;
    const __nv_bfloat16* aP = A + (size_t)(m0 + rowA) * lda;
    const __nv_bfloat16* bP = B + (size_t)(n0 + rowB) * ldb;
    const uint32_t rowABy = (uint32_t)rowA * 128u;
    const uint32_t rowBBy = (uint32_t)rowB * 128u;

    auto stage = [&](int st, int slot) {
        const uint32_t so = sbase + (uint32_t)slot * STG64;
        #pragma unroll
        for (int j = 0; j < 2; j++) {
            const int ch = cgA + j;
            CP16(so + rowABy + ((uint32_t)(ch ^ rkA) << 4), aP + st * 64 + ch * 8);
        }
        #pragma unroll
        for (int j = 0; j < 4; j++) {
            const int ch = cgB + j;
            CP16(so + 8192u + rowBBy + ((uint32_t)(ch ^ rkB) << 4),
                 bP + st * 64 + ch * 8);
        }
        CP_COMMIT();
    };

    uint32_t aOff[2], bOff[2];
    #pragma unroll
    for (int mi = 0; mi < 2; mi++)
        aOff[mi] = (uint32_t)((wm * 32 + mi * 16 + (lane & 15)) * 128);
    #pragma unroll
    for (int nj = 0; nj < 2; nj++)
        bOff[nj] = (uint32_t)((wn * 32 + nj * 16 + (lane & 7) +
                               ((lane & 16) >> 1)) * 128) + 8192u;
    const uint32_t lk = (uint32_t)(lane & 7);

    float acc[2][4][4];
    #pragma unroll
    for (int i = 0; i < 2; i++)
        #pragma unroll
        for (int j = 0; j < 4; j++)
            #pragma unroll
            for (int q = 0; q < 4; q++) acc[i][j][q] = 0.f;

    const int iters = kLen >> 6;

    #pragma unroll
    for (int p = 0; p < 2; p++)
        if (p < iters) stage(p, p);

    int slot = 0, nslot = (iters >= 3) ? 2 : 0;
    for (int it = 0; it < iters; it++) {
        if (it == iters - 1) { CP_WAIT0(); } else { CP_WAIT1(); }
        __syncthreads();

        if (it + 2 < iters) {
            stage(it + 2, nslot);
            nslot = (nslot == 2) ? 0 : nslot + 1;
        }

        const uint32_t sS = sbase + (uint32_t)slot * STG64;
        #pragma unroll
        for (int ks = 0; ks < 4; ks++) {
            const uint32_t swA = (uint32_t)((ks * 2 + (lane >> 4)) ^ lk) << 4;
            const uint32_t swB = (uint32_t)((ks * 2 + ((lane >> 3) & 1)) ^ lk) << 4;
            uint32_t a[2][4];
            #pragma unroll
            for (int mi = 0; mi < 2; mi++)
                LDSM_X4(a[mi][0], a[mi][1], a[mi][2], a[mi][3],
                        sS + aOff[mi] + swA);
            uint32_t b[4][2];
            #pragma unroll
            for (int nj = 0; nj < 2; nj++) {
                uint32_t r0, r1, r2, r3;
                LDSM_X4(r0, r1, r2, r3, sS + bOff[nj] + swB);
                b[2 * nj][0] = r0; b[2 * nj][1] = r1;
                b[2 * nj + 1][0] = r2; b[2 * nj + 1][1] = r3;
            }
            #pragma unroll
            for (int mi = 0; mi < 2; mi++)
                #pragma unroll
                for (int ni = 0; ni < 4; ni++)
                    MMA_BF16(acc[mi][ni], a[mi][0], a[mi][1], a[mi][2], a[mi][3],
                             b[ni][0], b[ni][1]);
        }
        slot = (slot == 2) ? 0 : slot + 1;
    }

    const int er = lane >> 2;
    const int ec = (lane & 3) * 2;
    #pragma unroll
    for (int mi = 0; mi < 2; mi++) {
        int gm = m0 + wm * 32 + mi * 16 + er;
        #pragma unroll
        for (int ni = 0; ni < 4; ni++) {
            int gn = n0 + wn * 32 + ni * 8 + ec;
            #pragma unroll
            for (int half = 0; half < 2; half++)
                epi_store(C, ldc, gm + half * 8, gn,
                          acc[mi][ni][half * 2], acc[mi][ni][half * 2 + 1],
                          epi, bias, resid);
        }
    }
}

// ---------------------------------------------------------------------------
// Merged weight conversion
// ---------------------------------------------------------------------------
#define N1Q (2 * DI * DM / 4)
#define N3Q (DM * DI / 4)
#define N2Q (DI * DTR / 4)
#define NXQ (128 * DI / 4)

__global__ void cvt_all_kernel(const float* __restrict__ w1,
                               const float* __restrict__ w3,
                               const float* __restrict__ w2,
                               const float* __restrict__ wx,
                               __nv_bfloat16* __restrict__ o1,
                               __nv_bfloat16* __restrict__ o3,
                               __nv_bfloat16* __restrict__ o2,
                               __nv_bfloat16* __restrict__ ox)
{
    int i = blockIdx.x * blockDim.x + threadIdx.x;
    const float* src;
    __nv_bfloat16* dst;
    int j = i;
    if (i < N1Q)                        { src = w1; dst = o1; }
    else if ((j = i - N1Q) < N3Q)       { src = w3; dst = o3; }
    else if ((j = i - N1Q - N3Q) < N2Q) { src = w2; dst = o2; }
    else {
        j = i - N1Q - N3Q - N2Q;
        if (j >= NXQ) return;
        int rowx = (j * 4) / DI;
        uint2 o;
        if (rowx < 96) {
            float4 v = *(const float4*)(wx + (size_t)j * 4);
            o = make_uint2(pack_bf2(v.x, v.y), pack_bf2(v.z, v.w));
        } else {
            o = make_uint2(0u, 0u);
        }
        *(uint2*)(ox + (size_t)j * 4) = o;
        return;
    }
    float4 v = *(const float4*)(src + (size_t)j * 4);
    *(uint2*)(dst + (size_t)j * 4) =
        make_uint2(pack_bf2(v.x, v.y), pack_bf2(v.z, v.w));
}

// ---------------------------------------------------------------------------
__global__ void rmsnorm_kernel(const float* __restrict__ x,
                               const float* __restrict__ w,
                               __nv_bfloat16* __restrict__ out)
{
    const int row = blockIdx.x;
    const int tid = threadIdx.x;
    const float* xr = x + (size_t)row * DM;

    float4 v = *(const float4*)(xr + tid * 4);
    float s = v.x * v.x + v.y * v.y + v.z * v.z + v.w * v.w;
    #pragma unroll
    for (int o = 16; o; o >>= 1) s += __shfl_xor_sync(0xffffffffu, s, o);

    __shared__ float sm[8];
    if ((tid & 31) == 0) sm[tid >> 5] = s;
    __syncthreads();
    float tot = sm[0] + sm[1] + sm[2] + sm[3] + sm[4] + sm[5] + sm[6] + sm[7];
    float scale = rsqrtf(tot * (1.f / DM) + 1e-6f);

    float4 wv = *(const float4*)(w + tid * 4);
    *(uint2*)(out + (size_t)row * DM + tid * 4) =
        make_uint2(pack_bf2(v.x * scale * wv.x, v.y * scale * wv.y),
                   pack_bf2(v.z * scale * wv.z, v.w * scale * wv.w));
}

// ---------------------------------------------------------------------------
__global__ void conv_silu_kernel(const __nv_bfloat16* __restrict__ xzb,
                                 const float* __restrict__ cw,
                                 const float* __restrict__ cb,
                                 __nv_bfloat16* __restrict__ ub)
{
    int gid = blockIdx.x * blockDim.x + threadIdx.x;
    if (gid >= R_TOT * DI) return;
    int d   = gid & (DI - 1);
    int row = gid >> 11;
    int t   = row & 1023;

    float acc = cb[d];
    #pragma unroll
    for (int j = 0; j < 4; j++) {
        int tt = t - 3 + j;
        if (tt >= 0)
            acc = fmaf(__bfloat162float(xzb[(size_t)(row - 3 + j) * (2 * DI) + d]),
                       cw[d * 4 + j], acc);
    }
    float s = acc / (1.f + __expf(-acc));
    ub[gid] = __float2bfloat16(s);
}

// ---------------------------------------------------------------------------
__global__ void xproj_reduce(const float* __restrict__ partial,
                             __nv_bfloat16* __restrict__ projb)
{
    int idx = blockIdx.x * blockDim.x + threadIdx.x;
    if (idx >= R_TOT * PSTR) return;
    float s = 0.f;
    #pragma unroll
    for (int p = 0; p < XS2; p++)
        s += partial[(size_t)p * R_TOT * PSTR + idx];
    projb[idx] = __float2bfloat16(s);
}

// ---------------------------------------------------------------------------
// Selective scan, ONE WAVE (r14 variant): 128 blocks x 512 thr, 32 ch/block.
// ---------------------------------------------------------------------------
__global__ void __launch_bounds__(512)
scan_kernel(const float* __restrict__ dt,
            const __nv_bfloat16* __restrict__ ub,
            const __nv_bfloat16* __restrict__ pjb,
            const __nv_bfloat16* __restrict__ xzb,
            const float* __restrict__ A_log,
            const float* __restrict__ D_diag,
            __nv_bfloat16* __restrict__ yb)
{
    __shared__ float2 s_du[TCH][36];
    __shared__ float2 s_bc[TCH][18];
    __shared__ float  s_z [TCH][40];
    __shared__ float  s_y [TCH][40];

    const int tid  = threadIdx.x;
    const int n    = tid & 15;
    const int g    = tid >> 4;          // 0..31 channel
    const int dblk = blockIdx.x & 63;
    const int b    = blockIdx.x >> 6;
    const int d0   = dblk * 32;
    const int d    = d0 + g;
    const int bbase = b * 1024;

    const float Adn = -__expf(A_log[d * DST + n]);
    const float Dd  = D_diag[d];

    const int lr  = tid >> 3;           // 0..63 row (t)
    const int lc4 = (tid & 7) * 4;      // 4 channels

    float state = 0.f;
    for (int c = 0; c < 1024 / TCH; c++) {
        const int t0 = c * TCH;
        const size_t grow = (size_t)(bbase + t0 + lr);

        float4 dv = *(const float4*)(dt + grow * DI + d0 + lc4);
        uint2 uu = *(const uint2*)(ub + grow * DI + d0 + lc4);
        __nv_bfloat162 u01 = *(__nv_bfloat162*)&uu.x;
        __nv_bfloat162 u23 = *(__nv_bfloat162*)&uu.y;
        s_du[lr][lc4 + 0] = make_float2(dv.x, __bfloat162float(u01.x));
        s_du[lr][lc4 + 1] = make_float2(dv.y, __bfloat162float(u01.y));
        s_du[lr][lc4 + 2] = make_float2(dv.z, __bfloat162float(u23.x));
        s_du[lr][lc4 + 3] = make_float2(dv.w, __bfloat162float(u23.y));

        uint2 zz = *(const uint2*)(xzb + grow * (2 * DI) + DI + d0 + lc4);
        __nv_bfloat162 z01 = *(__nv_bfloat162*)&zz.x;
        __nv_bfloat162 z23 = *(__nv_bfloat162*)&zz.y;
        s_z[lr][lc4 + 0] = __bfloat162float(z01.x);
        s_z[lr][lc4 + 1] = __bfloat162float(z01.y);
        s_z[lr][lc4 + 2] = __bfloat162float(z23.x);
        s_z[lr][lc4 + 3] = __bfloat162float(z23.y);

        if (tid < 256) {                 // B/C shared across all 32 channels
            const int lrb = tid >> 2;
            const int lcb = (tid & 3) * 4;
            const size_t growb = (size_t)(bbase + t0 + lrb);
            uint2 bb = *(const uint2*)(pjb + growb * PSTR + 64 + lcb);
            uint2 cc = *(const uint2*)(pjb + growb * PSTR + 80 + lcb);
            __nv_bfloat162 b01 = *(__nv_bfloat162*)&bb.x;
            __nv_bfloat162 b23 = *(__nv_bfloat162*)&bb.y;
            __nv_bfloat162 c01 = *(__nv_bfloat162*)&cc.x;
            __nv_bfloat162 c23 = *(__nv_bfloat162*)&cc.y;
            s_bc[lrb][lcb + 0] = make_float2(__bfloat162float(b01.x), __bfloat162float(c01.x));
            s_bc[lrb][lcb + 1] = make_float2(__bfloat162float(b01.y), __bfloat162float(c01.y));
            s_bc[lrb][lcb + 2] = make_float2(__bfloat162float(b23.x), __bfloat162float(c23.x));
            s_bc[lrb][lcb + 3] = make_float2(__bfloat162float(b23.y), __bfloat162float(c23.y));
        }
        __syncthreads();

        #pragma unroll 8
        for (int t = 0; t < TCH; t++) {
            float2 du = s_du[t][g];
            float2 bc = s_bc[t][n];

            float dA = __expf(du.x * Adn);
            state = fmaf(dA, state, (du.x * du.y) * bc.x);

            float part = state * bc.y;
            part += __shfl_xor_sync(0xffffffffu, part, 1);
            part += __shfl_xor_sync(0xffffffffu, part, 2);
            part += __shfl_xor_sync(0xffffffffu, part, 4);
            part += __shfl_xor_sync(0xffffffffu, part, 8);

            if (n == 0) {
                float zv = s_z[t][g];
                float sz = zv / (1.f + __expf(-zv));
                s_y[t][g] = (part + Dd * du.y) * sz;
            }
        }
        __syncthreads();

        float4 v = *(const float4*)&s_y[lr][lc4];
        *(uint2*)(yb + grow * DI + d0 + lc4) =
            make_uint2(pack_bf2(v.x, v.y), pack_bf2(v.z, v.w));
    }
}

// ---------------------------------------------------------------------------
extern "C" void kernel_launch(void* const* d_in, const int* in_sizes, int n_in,
                              void* d_out, int out_size)
{
    const float* x          = (const float*)d_in[0];
    const float* norm_w     = (const float*)d_in[1];
    const float* in_proj_w  = (const float*)d_in[2];
    const float* conv_w     = (const float*)d_in[3];
    const float* conv_b     = (const float*)d_in[4];
    const float* x_proj_w   = (const float*)d_in[5];
    const float* dt_proj_w  = (const float*)d_in[6];
    const float* dt_proj_b  = (const float*)d_in[7];
    const float* A_log      = (const float*)d_in[8];
    const float* D_diag     = (const float*)d_in[9];
    const float* out_proj_w = (const float*)d_in[10];
    float* out = (float*)d_out;

    float *projp, *dtb;
    __nv_bfloat16 *xzb, *xnb, *ub, *pjb, *yb, *w1b, *w2b, *w3b, *wxb;
    cudaGetSymbolAddress((void**)&projp, g_projp);
    cudaGetSymbolAddress((void**)&dtb,   g_dt);
    cudaGetSymbolAddress((void**)&xzb,   g_xzb);
    cudaGetSymbolAddress((void**)&xnb,   g_xnb);
    cudaGetSymbolAddress((void**)&ub,    g_ub);
    cudaGetSymbolAddress((void**)&pjb,   g_pjb);
    cudaGetSymbolAddress((void**)&yb,    g_yb);
    cudaGetSymbolAddress((void**)&w1b,   g_w1b);
    cudaGetSymbolAddress((void**)&w2b,   g_w2b);
    cudaGetSymbolAddress((void**)&w3b,   g_w3b);
    cudaGetSymbolAddress((void**)&wxb,   g_wxb);

    cudaFuncSetAttribute(gemm_cp2, cudaFuncAttributeMaxDynamicSharedMemorySize,
                         SMEM_DYN2);
    cudaFuncSetAttribute(gemm64, cudaFuncAttributeMaxDynamicSharedMemorySize,
                         SMEM_DYN64);

    const int NTOT = N1Q + N3Q + N2Q + NXQ;

    cvt_all_kernel<<<(NTOT + 255) / 256, 256>>>(in_proj_w, out_proj_w,
                                                dt_proj_w, x_proj_w,
                                                w1b, w3b, w2b, wxb);
    rmsnorm_kernel<<<R_TOT, 256>>>(x, norm_w, xnb);
    gemm_cp2<<<dim3(32, 16, 1), 256, SMEM_DYN2>>>(
        xnb, DM, w1b, DM, (float*)xzb, 2 * DI, 0, DM, 4, nullptr, nullptr);
    conv_silu_kernel<<<(R_TOT * DI) / 256, 256>>>(xzb, conv_w, conv_b, ub);
    gemm_cp2<<<dim3(1, 16, XS2), 256, SMEM_DYN2>>>(
        ub, DI, wxb, DI, projp, PSTR, (size_t)R_TOT * PSTR,
        DI / XS2, 0, nullptr, nullptr);
    xproj_reduce<<<(R_TOT * PSTR + 255) / 256, 256>>>(projp, pjb);
    gemm_cp2<<<dim3(16, 16, 1), 256, SMEM_DYN2>>>(
        pjb, PSTR, w2b, DTR, dtb, DI, 0, DTR, 1, dt_proj_b, nullptr);
    scan_kernel<<<128, 512>>>(dtb, ub, pjb, xzb, A_log, D_diag, yb);
    gemm64<<<dim3(8, 32), 256, SMEM_DYN64>>>(
        yb, DI, w3b, DI, out, DM, DI, 2, nullptr, x);
}